// round 5
// baseline (speedup 1.0000x reference)
#include <cuda_runtime.h>

#define BS    64
#define SL    8192
#define EDIM  64
#define DDIM  64
#define VOCAB 1088
#define NVAL  64
#define SPLIT 16
#define CHUNK (SL / SPLIT)          // 512
#define GRID  (BS * SPLIT)          // 1024
#define NTBL  68                    // 17 vocab-tiles x 4 batch-tiles

// Scratch (no allocations allowed)
__device__ float g_SK[BS * VOCAB];
__device__ float g_SV[BS * NVAL];
__device__ float g_Pz[BS * SPLIT];
__device__ float g_Pb[BS * SPLIT * NVAL];
__device__ int   g_cnt[BS];      // per-batch combine counter (self-reset)
__device__ int   g_tbl_done;     // table tiles published (self-reset)
__device__ int   g_fin;          // finished blocks (self-reset)

struct TablesSh {
    float big[64 * 65];          // Wq -> Wk_hi -> embK tile (padded)
    float Eq [16 * 64];
    float Qs [16 * 64];
    float Qks[16 * 64];
    int   qsh[16];
};
struct AttnSh {
    float SKs[VOCAB];
    float SVs[NVAL];
    float bins[8][NVAL];
    float red[8];
};
union ShUnion { TablesSh t; AttnSh a; };

// ---------------------------------------------------------------------------
// One fused kernel. Blocks 0..67 build the score tables; ALL blocks first put
// their 4MB of index loads in flight (overlapping table compute), spin on the
// table-done counter, then run the exp-histogram + split-combine.
// ---------------------------------------------------------------------------
__global__ __launch_bounds__(256, 6) void fused_kernel(
    const int*   __restrict__ x,
    const int*   __restrict__ q,
    const float* __restrict__ embK,
    const float* __restrict__ Wk_w,   // (64, 128) row-major
    const float* __restrict__ Wq_w,   // (64, 64) row-major
    const float* __restrict__ Wq_b,
    float*       __restrict__ out)
{
    __shared__ ShUnion sh;
    __shared__ int lastFlag;

    const int bid  = blockIdx.x;
    const int b    = bid >> 4;
    const int sp   = bid & 15;
    const int tid  = threadIdx.x;
    const int warp = tid >> 5;
    const int lane = tid & 31;

    // ---- Prefetch this block's index data (DRAM) — stays in flight ----
    const int* kp = x + (size_t)b * 2 * SL + sp * CHUNK;
    const int* vp = kp + SL;
    const int2 k2 = __ldg(reinterpret_cast<const int2*>(kp) + tid);
    const int2 w2 = __ldg(reinterpret_cast<const int2*>(vp) + tid);

    // ---- Producer phase: blocks 0..67 build table tiles ----
    if (bid < NTBL) {
        const int bt = bid & 3;          // batch tile (16 batches)
        const int vt = bid >> 2;         // vocab tile (64 rows)
        const int b0 = bt * 16;
        const int v0 = vt * 64;
        TablesSh& T = sh.t;

        if (tid < 16) T.qsh[tid] = q[b0 + tid];
        for (int i = tid; i < 64 * 64; i += 256)
            T.big[(i >> 6) * 65 + (i & 63)] = Wq_w[i];
        __syncthreads();
        for (int i = tid; i < 16 * 64; i += 256)
            T.Eq[i] = embK[(size_t)T.qsh[i >> 6] * EDIM + (i & 63)];
        __syncthreads();

        // Q = Eq . Wq rows + bias
        for (int idx = tid; idx < 1024; idx += 256) {
            const int bl = idx >> 6, d = idx & 63;
            float acc = Wq_b[d];
            #pragma unroll
            for (int e = 0; e < EDIM; e++)
                acc = fmaf(T.Eq[bl * 64 + e], T.big[d * 65 + e], acc);
            T.Qs[idx] = acc;
        }
        __syncthreads();

        // Wk_hi into big
        for (int i = tid; i < 64 * 64; i += 256)
            T.big[(i >> 6) * 65 + (i & 63)] = Wk_w[(i >> 6) * 128 + 64 + (i & 63)];
        __syncthreads();

        // Qk; vt==0 blocks also emit SV
        for (int idx = tid; idx < 1024; idx += 256) {
            const int bl = idx >> 6, e = idx & 63;
            float acc = 0.f;
            #pragma unroll
            for (int d = 0; d < DDIM; d++)
                acc = fmaf(T.big[d * 65 + e], T.Qs[bl * 64 + d], acc);
            T.Qks[idx] = acc * 0.125f;
        }
        if (vt == 0) {
            for (int idx = tid; idx < 1024; idx += 256) {
                const int bl = idx >> 6, n = idx & 63;
                float acc = 0.f;
                #pragma unroll
                for (int d = 0; d < DDIM; d++)
                    acc = fmaf(Wk_w[d * 128 + n], T.Qs[bl * 64 + d], acc);
                g_SV[(b0 + bl) * NVAL + n] = acc * 0.125f;
            }
        }
        __syncthreads();

        // embK vocab tile into big
        for (int i = tid; i < 64 * 64; i += 256)
            T.big[(i >> 6) * 65 + (i & 63)] = embK[(size_t)v0 * EDIM + i];
        __syncthreads();

        // SK tile, register-tiled 4 batches/thread, coalesced writes
        {
            const int vl  = tid & 63;
            const int blq = tid >> 6;
            float acc[4] = {0.f, 0.f, 0.f, 0.f};
            #pragma unroll
            for (int e = 0; e < EDIM; e++) {
                const float ev = T.big[vl * 65 + e];
                #pragma unroll
                for (int j = 0; j < 4; j++)
                    acc[j] = fmaf(ev, T.Qks[(blq + 4 * j) * 64 + e], acc[j]);
            }
            #pragma unroll
            for (int j = 0; j < 4; j++)
                g_SK[(size_t)(b0 + blq + 4 * j) * VOCAB + v0 + vl] = acc[j];
        }

        // Publish: all threads fence their stores, then one release-count
        __threadfence();
        __syncthreads();
        if (tid == 0) atomicAdd(&g_tbl_done, 1);
    }

    // ---- Barrier: wait for all 68 table tiles ----
    if (tid == 0) {
        while (*(volatile int*)&g_tbl_done < NTBL) __nanosleep(64);
        __threadfence();     // acquire
    }
    __syncthreads();

    // ---- Consumer phase ----
    AttnSh& A = sh.a;
    {
        const float4* src = reinterpret_cast<const float4*>(g_SK + (size_t)b * VOCAB);
        float4* dst = reinterpret_cast<float4*>(A.SKs);
        for (int i = tid; i < VOCAB / 4; i += 256) dst[i] = src[i];
    }
    if (tid < NVAL) A.SVs[tid] = g_SV[b * NVAL + tid];
    for (int i = tid; i < 8 * NVAL; i += 256) (&A.bins[0][0])[i] = 0.f;
    __syncthreads();

    const int v0i = w2.x - NVAL, v1i = w2.y - NVAL;
    const float e0 = __expf(A.SKs[k2.x] + A.SVs[v0i]);
    const float e1 = __expf(A.SKs[k2.y] + A.SVs[v1i]);
    float z = e0 + e1;
    atomicAdd(&A.bins[warp][v0i], e0);
    atomicAdd(&A.bins[warp][v1i], e1);

    #pragma unroll
    for (int o = 16; o > 0; o >>= 1) z += __shfl_xor_sync(0xffffffffu, z, o);
    if (lane == 0) A.red[warp] = z;
    __syncthreads();

    if (tid < NVAL) {
        float bsum = 0.f;
        #pragma unroll
        for (int w = 0; w < 8; w++) bsum += A.bins[w][tid];
        g_Pb[(b * SPLIT + sp) * NVAL + tid] = bsum;
    }
    if (tid == 0) {
        float Z = 0.f;
        #pragma unroll
        for (int w = 0; w < 8; w++) Z += A.red[w];
        g_Pz[b * SPLIT + sp] = Z;
    }
    __threadfence();
    __syncthreads();

    if (tid == 0) {
        const int old = atomicAdd(&g_cnt[b], 1);
        lastFlag = (old == SPLIT - 1) ? 1 : 0;
        __threadfence();
    }
    __syncthreads();

    if (lastFlag) {
        if (tid < NVAL) {
            volatile float* vPz = g_Pz + b * SPLIT;
            volatile float* vPb = g_Pb + (size_t)b * SPLIT * NVAL;
            float Zt = 0.f, num = 0.f;
            #pragma unroll
            for (int s2 = 0; s2 < SPLIT; s2++) {
                Zt  += vPz[s2];
                num += vPb[s2 * NVAL + tid];
            }
            out[b * NVAL + tid] = num / Zt;
        }
        __syncthreads();
        if (tid == 0) g_cnt[b] = 0;                 // re-arm per-batch counter
    }

    // ---- Global re-arm for graph replay: last of all 1024 blocks resets ----
    if (tid == 0) {
        const int old = atomicAdd(&g_fin, 1);
        if (old == GRID - 1) {
            g_tbl_done = 0;
            g_fin = 0;
            __threadfence();
        }
    }
}

// ---------------------------------------------------------------------------
// Inputs (metadata order): x(int32), q(int32), embK, Wk_w, Wk_b, Wq_w, Wq_b.
// Wk_b is softmax-invariant (constant per batch) and intentionally unused.
// ---------------------------------------------------------------------------
extern "C" void kernel_launch(void* const* d_in, const int* in_sizes, int n_in,
                              void* d_out, int out_size)
{
    const int*   x    = (const int*)  d_in[0];
    const int*   q    = (const int*)  d_in[1];
    const float* embK = (const float*)d_in[2];
    const float* Wk_w = (const float*)d_in[3];
    const float* Wq_w = (const float*)d_in[5];
    const float* Wq_b = (const float*)d_in[6];
    float* out = (float*)d_out;

    fused_kernel<<<GRID, 256>>>(x, q, embK, Wk_w, Wq_w, Wq_b, out);
}

// round 6
// speedup vs baseline: 1.6146x; 1.6146x over previous
#include <cuda_runtime.h>

#define BS    64
#define SL    8192
#define EDIM  64
#define DDIM  64
#define VOCAB 1088
#define NVAL  64
#define SPLIT 8
#define CHUNK (SL / SPLIT)          // 1024
#define EPT   4                     // int4 per thread

// Scratch (no allocations allowed)
__device__ float g_SK[BS * VOCAB];
__device__ float g_SV[BS * NVAL];
__device__ float g_Pz[BS * SPLIT];
__device__ float g_Pb[BS * SPLIT * NVAL];
__device__ int   g_cnt[BS];   // zero-init; self-reset by combining block

// ---------------------------------------------------------------------------
// Kernel A: per-batch score tables, one block per batch (64 blocks, 256 thr).
// No redundant work; everything coalesced; GEMVs via warp rows + shfl.
//   Q[d]  = embK[q[b]] . Wq_w[d,:] + Wq_b[d]
//   Qk[e] = 0.125 * sum_d Wk_w[d,64+e] * Q[d]
//   SV[n] = 0.125 * sum_d Wk_w[d,n]    * Q[d]
//   SK[v] = embK[v] . Qk          (1088 rows, warp-per-row, embK streamed)
// ---------------------------------------------------------------------------
__global__ __launch_bounds__(256) void tables_kernel(
    const int*   __restrict__ q,
    const float* __restrict__ embK,
    const float* __restrict__ Wk_w,   // (64, 128) row-major
    const float* __restrict__ Wq_w,   // (64, 64) row-major
    const float* __restrict__ Wq_b)
{
    const int b    = blockIdx.x;
    const int tid  = threadIdx.x;
    const int warp = tid >> 5;
    const int lane = tid & 31;

    __shared__ float eqs[EDIM];
    __shared__ float Qs [DDIM];
    __shared__ float Qks[EDIM];
    __shared__ float part[256];

    if (tid < EDIM) eqs[tid] = embK[(size_t)q[b] * EDIM + tid];
    __syncthreads();

    // ---- Q: warp w computes rows d = w*8 .. w*8+7 (float2 lanes + reduce) ----
    {
        const float2 eq2 = reinterpret_cast<const float2*>(eqs)[lane];
        #pragma unroll
        for (int r = 0; r < 8; r++) {
            const int d = warp * 8 + r;
            const float2 w2 = reinterpret_cast<const float2*>(Wq_w + (size_t)d * EDIM)[lane];
            float a = w2.x * eq2.x + w2.y * eq2.y;
            #pragma unroll
            for (int o = 16; o > 0; o >>= 1) a += __shfl_xor_sync(0xffffffffu, a, o);
            if (lane == 0) Qs[d] = a + Wq_b[d];
        }
    }
    __syncthreads();

    // ---- Qk (tid 0..127) and SV (tid 128..255), 2-way d-split, coalesced ----
    {
        const int e  = tid & 63;
        const int pg = (tid >> 6) & 1;          // d-half
        const int d0 = pg * 32;
        const bool isQk = (tid < 128);
        const float* col = Wk_w + (isQk ? (64 + e) : e);
        float acc = 0.f;
        #pragma unroll
        for (int d = 0; d < 32; d++)
            acc = fmaf(col[(size_t)(d0 + d) * 128], Qs[d0 + d], acc);
        part[tid] = acc;
    }
    __syncthreads();
    if (tid < EDIM)
        Qks[tid] = (part[tid] + part[tid + 64]) * 0.125f;
    if (tid >= 128 && tid < 192)
        g_SV[b * NVAL + (tid - 128)] = (part[tid] + part[tid + 64]) * 0.125f;
    __syncthreads();

    // ---- SK: warp-per-row over 1088 vocab rows, Qk in registers ----
    {
        const float2 qk2 = reinterpret_cast<const float2*>(Qks)[lane];
        float* dst = g_SK + (size_t)b * VOCAB;
        for (int v = warp; v < VOCAB; v += 8) {
            const float2 e2 = reinterpret_cast<const float2*>(embK + (size_t)v * EDIM)[lane];
            float a = e2.x * qk2.x + e2.y * qk2.y;
            #pragma unroll
            for (int o = 16; o > 0; o >>= 1) a += __shfl_xor_sync(0xffffffffu, a, o);
            if (lane == 0) dst[v] = a;
        }
    }
}

// ---------------------------------------------------------------------------
// Kernel B: streaming exp-histogram (no max subtraction; |score| <~ 4).
// grid = 64 batches x 8 splits (512 blocks), 256 threads, 4 elems/thread.
// Index loads issued BEFORE the table fill (DRAM latency overlaps L2 fill).
// Last block per batch linearly combines the 8 partials.
// ---------------------------------------------------------------------------
__global__ __launch_bounds__(256) void attn_kernel(
    const int* __restrict__ x,
    float*     __restrict__ out)
{
    const int b    = blockIdx.x >> 3;
    const int sp   = blockIdx.x & 7;
    const int tid  = threadIdx.x;
    const int warp = tid >> 5;
    const int lane = tid & 31;

    __shared__ float SKs[VOCAB];
    __shared__ float SVs[NVAL];
    __shared__ float bins[8][NVAL];     // warp-replicated histograms
    __shared__ float red[8];
    __shared__ int   lastFlag;

    // Prefetch index data first
    const int* kp = x + (size_t)b * 2 * SL + sp * CHUNK;
    const int* vp = kp + SL;
    const int4 k4 = __ldg(reinterpret_cast<const int4*>(kp) + tid);
    const int4 w4 = __ldg(reinterpret_cast<const int4*>(vp) + tid);

    // Table fill (vectorized)
    {
        const float4* src = reinterpret_cast<const float4*>(g_SK + (size_t)b * VOCAB);
        float4* dst = reinterpret_cast<float4*>(SKs);
        for (int i = tid; i < VOCAB / 4; i += 256) dst[i] = src[i];
    }
    if (tid < NVAL) SVs[tid] = g_SV[b * NVAL + tid];
    for (int i = tid; i < 8 * NVAL; i += 256) (&bins[0][0])[i] = 0.f;
    __syncthreads();

    const int kk[EPT] = {k4.x, k4.y, k4.z, k4.w};
    const int vv[EPT] = {w4.x - NVAL, w4.y - NVAL, w4.z - NVAL, w4.w - NVAL};

    float z = 0.f;
    #pragma unroll
    for (int i = 0; i < EPT; i++) {
        const float e = __expf(SKs[kk[i]] + SVs[vv[i]]);
        z += e;
        atomicAdd(&bins[warp][vv[i]], e);
    }
    #pragma unroll
    for (int o = 16; o > 0; o >>= 1) z += __shfl_xor_sync(0xffffffffu, z, o);
    if (lane == 0) red[warp] = z;
    __syncthreads();

    if (tid < NVAL) {
        float bsum = 0.f;
        #pragma unroll
        for (int w = 0; w < 8; w++) bsum += bins[w][tid];
        g_Pb[(b * SPLIT + sp) * NVAL + tid] = bsum;
    }
    if (tid == 0) {
        float Z = 0.f;
        #pragma unroll
        for (int w = 0; w < 8; w++) Z += red[w];
        g_Pz[b * SPLIT + sp] = Z;
    }
    __syncthreads();

    if (tid == 0) {
        __threadfence();                            // publish partials (release)
        const int old = atomicAdd(&g_cnt[b], 1);
        lastFlag = (old == SPLIT - 1) ? 1 : 0;
        __threadfence();                            // acquire
    }
    __syncthreads();

    if (lastFlag) {
        if (tid < NVAL) {
            volatile float* vPz = g_Pz + b * SPLIT;
            volatile float* vPb = g_Pb + (size_t)b * SPLIT * NVAL;
            float Zt = 0.f, num = 0.f;
            #pragma unroll
            for (int s2 = 0; s2 < SPLIT; s2++) {
                Zt  += vPz[s2];
                num += vPb[s2 * NVAL + tid];
            }
            out[b * NVAL + tid] = num / Zt;
        }
        __syncthreads();
        if (tid == 0) g_cnt[b] = 0;                 // re-arm for next replay
    }
}

// ---------------------------------------------------------------------------
// Inputs (metadata order): x(int32), q(int32), embK, Wk_w, Wk_b, Wq_w, Wq_b.
// Wk_b is softmax-invariant (constant per batch) and intentionally unused.
// ---------------------------------------------------------------------------
extern "C" void kernel_launch(void* const* d_in, const int* in_sizes, int n_in,
                              void* d_out, int out_size)
{
    const int*   x    = (const int*)  d_in[0];
    const int*   q    = (const int*)  d_in[1];
    const float* embK = (const float*)d_in[2];
    const float* Wk_w = (const float*)d_in[3];
    const float* Wq_w = (const float*)d_in[5];
    const float* Wq_b = (const float*)d_in[6];
    float* out = (float*)d_out;

    tables_kernel<<<BS, 256>>>(q, embK, Wk_w, Wq_w, Wq_b);
    attn_kernel<<<BS * SPLIT, 256>>>(x, out);
}

// round 7
// speedup vs baseline: 2.3310x; 1.4437x over previous
#include <cuda_runtime.h>

#define BS    64
#define SL    8192
#define EDIM  64
#define DDIM  64
#define VOCAB 1088
#define NVAL  64
#define SPLIT 8
#define CHUNK (SL / SPLIT)          // 1024
#define EPT   4                     // int4 per thread

// Scratch (no allocations allowed)
__device__ float g_SK[BS * VOCAB];
__device__ float g_SV[BS * NVAL];
__device__ float g_Pz[BS * SPLIT];
__device__ float g_Pb[BS * SPLIT * NVAL];
__device__ int   g_cnt[BS];   // zero-init; self-reset by combining block

// ---------------------------------------------------------------------------
// Kernel A: per-batch score tables. grid = 64 batches x 4 tile-groups.
// No shuffle chains: every reduction is a 4-way shared-partial add.
//   Q[d]  = embK[q[b]] . Wq_w[d,:] + Wq_b[d]
//   Qk[e] = 0.125 * sum_d Wk_w[d,64+e] * Q[d]
//   SV[n] = 0.125 * sum_d Wk_w[d,n]    * Q[d]     (tg==0 blocks only)
//   SK[v] = embK[v] . Qk                          (tg handles tiles tg*4..+3; tg0 also tile 16)
// ---------------------------------------------------------------------------
__global__ __launch_bounds__(256) void tables_kernel(
    const int*   __restrict__ q,
    const float* __restrict__ embK,
    const float* __restrict__ Wk_w,   // (64, 128) row-major
    const float* __restrict__ Wq_w,   // (64, 64) row-major
    const float* __restrict__ Wq_b)
{
    const int b   = blockIdx.x >> 2;
    const int tg  = blockIdx.x & 3;
    const int tid = threadIdx.x;

    __shared__ float eqs[EDIM];
    __shared__ float Qs [DDIM];
    __shared__ float Qks[EDIM];
    __shared__ float part[256];
    __shared__ float tile[64 * 65];   // padded: conflict-free (v + c) banks

    if (tid < EDIM) eqs[tid] = embK[(size_t)q[b] * EDIM + tid];
    __syncthreads();

    // ---- Q: thread (d = tid>>2, seg = tid&3) -> 16-wide partial ----
    {
        const int d = tid >> 2, s = tid & 3;
        const float4* wrow = reinterpret_cast<const float4*>(Wq_w + (size_t)d * EDIM) + s * 4;
        float acc = 0.f;
        #pragma unroll
        for (int i = 0; i < 4; i++) {
            const float4 w4 = wrow[i];
            const int e = s * 16 + i * 4;
            acc += w4.x * eqs[e] + w4.y * eqs[e + 1] + w4.z * eqs[e + 2] + w4.w * eqs[e + 3];
        }
        part[tid] = acc;
    }
    __syncthreads();
    if (tid < DDIM)
        Qs[tid] = part[tid * 4] + part[tid * 4 + 1] + part[tid * 4 + 2] + part[tid * 4 + 3]
                + Wq_b[tid];
    __syncthreads();

    // ---- Qk: thread (dg = tid>>6, e = tid&63) -> 16-d partial, coalesced ----
    {
        const int dg = tid >> 6, e = tid & 63;
        float acc = 0.f;
        #pragma unroll
        for (int i = 0; i < 16; i++) {
            const int d = dg * 16 + i;
            acc = fmaf(Wk_w[(size_t)d * 128 + 64 + e], Qs[d], acc);
        }
        part[tid] = acc;
    }
    __syncthreads();
    if (tid < EDIM)
        Qks[tid] = (part[tid] + part[64 + tid] + part[128 + tid] + part[192 + tid]) * 0.125f;

    // ---- SV (tg==0 blocks only; block-uniform branch, extra syncs safe) ----
    if (tg == 0) {
        __syncthreads();
        const int dg = tid >> 6, e = tid & 63;
        float acc = 0.f;
        #pragma unroll
        for (int i = 0; i < 16; i++) {
            const int d = dg * 16 + i;
            acc = fmaf(Wk_w[(size_t)d * 128 + e], Qs[d], acc);
        }
        part[tid] = acc;
        __syncthreads();
        if (tid < NVAL)
            g_SV[b * NVAL + tid] = (part[tid] + part[64 + tid] + part[128 + tid] + part[192 + tid]) * 0.125f;
    }
    __syncthreads();                     // Qks (and part reuse) ready

    // ---- SK: 64-row embK tiles; Qks quarter cached in registers ----
    const int qtr = tid >> 6, v = tid & 63;
    float qk[16];
    #pragma unroll
    for (int i = 0; i < 16; i++) qk[i] = Qks[qtr * 16 + i];

    const int ntiles = (tg == 0) ? 5 : 4;
    for (int t = 0; t < ntiles; t++) {
        const int tile_id = (t < 4) ? (tg * 4 + t) : 16;
        const int v0 = tile_id * 64;

        __syncthreads();                 // previous iteration's tile reads done
        for (int i = tid; i < 4096; i += 256)
            tile[(i >> 6) * 65 + (i & 63)] = embK[(size_t)v0 * EDIM + i];
        __syncthreads();

        float acc = 0.f;
        #pragma unroll
        for (int i = 0; i < 16; i++)
            acc = fmaf(tile[v * 65 + qtr * 16 + i], qk[i], acc);
        part[qtr * 64 + v] = acc;
        __syncthreads();

        if (tid < 64)
            g_SK[(size_t)b * VOCAB + v0 + tid] =
                part[tid] + part[64 + tid] + part[128 + tid] + part[192 + tid];
    }
}

// ---------------------------------------------------------------------------
// Kernel B: streaming exp-histogram (no max subtraction; |score| small).
// grid = 64 batches x 8 splits (512 blocks), 256 threads, 4 elems/thread.
// Identical to R6 (best measured attn: 8.7us).
// ---------------------------------------------------------------------------
__global__ __launch_bounds__(256) void attn_kernel(
    const int* __restrict__ x,
    float*     __restrict__ out)
{
    const int b    = blockIdx.x >> 3;
    const int sp   = blockIdx.x & 7;
    const int tid  = threadIdx.x;
    const int warp = tid >> 5;
    const int lane = tid & 31;

    __shared__ float SKs[VOCAB];
    __shared__ float SVs[NVAL];
    __shared__ float bins[8][NVAL];     // warp-replicated histograms
    __shared__ float red[8];
    __shared__ int   lastFlag;

    // Prefetch index data first
    const int* kp = x + (size_t)b * 2 * SL + sp * CHUNK;
    const int* vp = kp + SL;
    const int4 k4 = __ldg(reinterpret_cast<const int4*>(kp) + tid);
    const int4 w4 = __ldg(reinterpret_cast<const int4*>(vp) + tid);

    // Table fill (vectorized)
    {
        const float4* src = reinterpret_cast<const float4*>(g_SK + (size_t)b * VOCAB);
        float4* dst = reinterpret_cast<float4*>(SKs);
        for (int i = tid; i < VOCAB / 4; i += 256) dst[i] = src[i];
    }
    if (tid < NVAL) SVs[tid] = g_SV[b * NVAL + tid];
    for (int i = tid; i < 8 * NVAL; i += 256) (&bins[0][0])[i] = 0.f;
    __syncthreads();

    const int kk[EPT] = {k4.x, k4.y, k4.z, k4.w};
    const int vv[EPT] = {w4.x - NVAL, w4.y - NVAL, w4.z - NVAL, w4.w - NVAL};

    float z = 0.f;
    #pragma unroll
    for (int i = 0; i < EPT; i++) {
        const float e = __expf(SKs[kk[i]] + SVs[vv[i]]);
        z += e;
        atomicAdd(&bins[warp][vv[i]], e);
    }
    #pragma unroll
    for (int o = 16; o > 0; o >>= 1) z += __shfl_xor_sync(0xffffffffu, z, o);
    if (lane == 0) red[warp] = z;
    __syncthreads();

    if (tid < NVAL) {
        float bsum = 0.f;
        #pragma unroll
        for (int w = 0; w < 8; w++) bsum += bins[w][tid];
        g_Pb[(b * SPLIT + sp) * NVAL + tid] = bsum;
    }
    if (tid == 0) {
        float Z = 0.f;
        #pragma unroll
        for (int w = 0; w < 8; w++) Z += red[w];
        g_Pz[b * SPLIT + sp] = Z;
    }
    __syncthreads();

    if (tid == 0) {
        __threadfence();                            // publish partials (release)
        const int old = atomicAdd(&g_cnt[b], 1);
        lastFlag = (old == SPLIT - 1) ? 1 : 0;
        __threadfence();                            // acquire
    }
    __syncthreads();

    if (lastFlag) {
        if (tid < NVAL) {
            volatile float* vPz = g_Pz + b * SPLIT;
            volatile float* vPb = g_Pb + (size_t)b * SPLIT * NVAL;
            float Zt = 0.f, num = 0.f;
            #pragma unroll
            for (int s2 = 0; s2 < SPLIT; s2++) {
                Zt  += vPz[s2];
                num += vPb[s2 * NVAL + tid];
            }
            out[b * NVAL + tid] = num / Zt;
        }
        __syncthreads();
        if (tid == 0) g_cnt[b] = 0;                 // re-arm for next replay
    }
}

// ---------------------------------------------------------------------------
// Inputs (metadata order): x(int32), q(int32), embK, Wk_w, Wk_b, Wq_w, Wq_b.
// Wk_b is softmax-invariant (constant per batch) and intentionally unused.
// ---------------------------------------------------------------------------
extern "C" void kernel_launch(void* const* d_in, const int* in_sizes, int n_in,
                              void* d_out, int out_size)
{
    const int*   x    = (const int*)  d_in[0];
    const int*   q    = (const int*)  d_in[1];
    const float* embK = (const float*)d_in[2];
    const float* Wk_w = (const float*)d_in[3];
    const float* Wq_w = (const float*)d_in[5];
    const float* Wq_b = (const float*)d_in[6];
    float* out = (float*)d_out;

    tables_kernel<<<BS * 4, 256>>>(q, embK, Wk_w, Wq_w, Wq_b);
    attn_kernel<<<BS * SPLIT, 256>>>(x, out);
}

// round 8
// speedup vs baseline: 2.3351x; 1.0017x over previous
#include <cuda_runtime.h>

#define BS    64
#define SL    8192
#define EDIM  64
#define DDIM  64
#define VOCAB 1088
#define NVAL  64
#define SPLIT 8
#define CHUNK (SL / SPLIT)          // 1024
#define EPT   4                     // int4 per thread

// Scratch (no allocations allowed)
__device__ float g_EK[BS * VOCAB];   // exp(SK)
__device__ float g_EV[BS * NVAL];    // exp(SV)
__device__ float g_Pb[BS * SPLIT * NVAL];
__device__ int   g_cnt[BS];   // zero-init; self-reset by combining block

// ---------------------------------------------------------------------------
// Kernel A: per-batch score tables, stored EXPONENTIATED.
// grid = 64 batches x 4 tile-groups. Same structure as R7 (measured good);
// only change: __expf at the final writes.
//   Q[d]  = embK[q[b]] . Wq_w[d,:] + Wq_b[d]
//   Qk[e] = 0.125 * sum_d Wk_w[d,64+e] * Q[d]
//   EV[n] = exp(0.125 * sum_d Wk_w[d,n] * Q[d])   (tg==0 blocks only)
//   EK[v] = exp(embK[v] . Qk)
// ---------------------------------------------------------------------------
__global__ __launch_bounds__(256) void tables_kernel(
    const int*   __restrict__ q,
    const float* __restrict__ embK,
    const float* __restrict__ Wk_w,   // (64, 128) row-major
    const float* __restrict__ Wq_w,   // (64, 64) row-major
    const float* __restrict__ Wq_b)
{
    const int b   = blockIdx.x >> 2;
    const int tg  = blockIdx.x & 3;
    const int tid = threadIdx.x;

    __shared__ float eqs[EDIM];
    __shared__ float Qs [DDIM];
    __shared__ float Qks[EDIM];
    __shared__ float part[256];
    __shared__ float tile[64 * 65];   // padded: conflict-free (v + c) banks

    if (tid < EDIM) eqs[tid] = embK[(size_t)q[b] * EDIM + tid];
    __syncthreads();

    // ---- Q: thread (d = tid>>2, seg = tid&3) -> 16-wide partial ----
    {
        const int d = tid >> 2, s = tid & 3;
        const float4* wrow = reinterpret_cast<const float4*>(Wq_w + (size_t)d * EDIM) + s * 4;
        float acc = 0.f;
        #pragma unroll
        for (int i = 0; i < 4; i++) {
            const float4 w4 = wrow[i];
            const int e = s * 16 + i * 4;
            acc += w4.x * eqs[e] + w4.y * eqs[e + 1] + w4.z * eqs[e + 2] + w4.w * eqs[e + 3];
        }
        part[tid] = acc;
    }
    __syncthreads();
    if (tid < DDIM)
        Qs[tid] = part[tid * 4] + part[tid * 4 + 1] + part[tid * 4 + 2] + part[tid * 4 + 3]
                + Wq_b[tid];
    __syncthreads();

    // ---- Qk: thread (dg = tid>>6, e = tid&63) -> 16-d partial, coalesced ----
    {
        const int dg = tid >> 6, e = tid & 63;
        float acc = 0.f;
        #pragma unroll
        for (int i = 0; i < 16; i++) {
            const int d = dg * 16 + i;
            acc = fmaf(Wk_w[(size_t)d * 128 + 64 + e], Qs[d], acc);
        }
        part[tid] = acc;
    }
    __syncthreads();
    if (tid < EDIM)
        Qks[tid] = (part[tid] + part[64 + tid] + part[128 + tid] + part[192 + tid]) * 0.125f;

    // ---- EV (tg==0 blocks only; block-uniform branch, extra syncs safe) ----
    if (tg == 0) {
        __syncthreads();
        const int dg = tid >> 6, e = tid & 63;
        float acc = 0.f;
        #pragma unroll
        for (int i = 0; i < 16; i++) {
            const int d = dg * 16 + i;
            acc = fmaf(Wk_w[(size_t)d * 128 + e], Qs[d], acc);
        }
        part[tid] = acc;
        __syncthreads();
        if (tid < NVAL)
            g_EV[b * NVAL + tid] =
                __expf((part[tid] + part[64 + tid] + part[128 + tid] + part[192 + tid]) * 0.125f);
    }
    __syncthreads();                     // Qks ready; part reusable

    // ---- EK: 64-row embK tiles; Qks quarter cached in registers ----
    const int qtr = tid >> 6, v = tid & 63;
    float qk[16];
    #pragma unroll
    for (int i = 0; i < 16; i++) qk[i] = Qks[qtr * 16 + i];

    const int ntiles = (tg == 0) ? 5 : 4;
    for (int t = 0; t < ntiles; t++) {
        const int tile_id = (t < 4) ? (tg * 4 + t) : 16;
        const int v0 = tile_id * 64;

        __syncthreads();                 // previous iteration's tile reads done
        for (int i = tid; i < 4096; i += 256)
            tile[(i >> 6) * 65 + (i & 63)] = embK[(size_t)v0 * EDIM + i];
        __syncthreads();

        float acc = 0.f;
        #pragma unroll
        for (int i = 0; i < 16; i++)
            acc = fmaf(tile[v * 65 + qtr * 16 + i], qk[i], acc);
        part[qtr * 64 + v] = acc;
        __syncthreads();

        if (tid < 64)
            g_EK[(size_t)b * VOCAB + v0 + tid] =
                __expf(part[tid] + part[64 + tid] + part[128 + tid] + part[192 + tid]);
    }
}

// ---------------------------------------------------------------------------
// Kernel B: pure gather-histogram. exp factored out: per element only
//   bins[warp][val] += EK[key]
// Partial numerator for bin n is EV[n]*Σbins (EV applied at combine);
// Z = Σ_n num[n], so no per-element z reduction at all.
// grid = 64 batches x 8 splits (512 blocks), 256 threads, 4 elems/thread.
// ---------------------------------------------------------------------------
__global__ __launch_bounds__(256) void attn_kernel(
    const int* __restrict__ x,
    float*     __restrict__ out)
{
    const int b    = blockIdx.x >> 3;
    const int sp   = blockIdx.x & 7;
    const int tid  = threadIdx.x;
    const int warp = tid >> 5;

    __shared__ float EKs[VOCAB];
    __shared__ float bins[8][NVAL];     // warp-replicated histograms
    __shared__ float num[NVAL];
    __shared__ int   lastFlag;

    // Prefetch index data first (DRAM) — overlaps table fill (L2)
    const int* kp = x + (size_t)b * 2 * SL + sp * CHUNK;
    const int* vp = kp + SL;
    const int4 k4 = __ldg(reinterpret_cast<const int4*>(kp) + tid);
    const int4 w4 = __ldg(reinterpret_cast<const int4*>(vp) + tid);

    // Table fill (vectorized, from L2)
    {
        const float4* src = reinterpret_cast<const float4*>(g_EK + (size_t)b * VOCAB);
        float4* dst = reinterpret_cast<float4*>(EKs);
        for (int i = tid; i < VOCAB / 4; i += 256) dst[i] = src[i];
    }
    for (int i = tid; i < 8 * NVAL; i += 256) (&bins[0][0])[i] = 0.f;
    __syncthreads();

    const int kk[EPT] = {k4.x, k4.y, k4.z, k4.w};
    const int vv[EPT] = {w4.x - NVAL, w4.y - NVAL, w4.z - NVAL, w4.w - NVAL};

    #pragma unroll
    for (int i = 0; i < EPT; i++)
        atomicAdd(&bins[warp][vv[i]], EKs[kk[i]]);
    __syncthreads();

    if (tid < NVAL) {
        float bsum = 0.f;
        #pragma unroll
        for (int w = 0; w < 8; w++) bsum += bins[w][tid];
        g_Pb[(b * SPLIT + sp) * NVAL + tid] = bsum;
    }
    __syncthreads();

    if (tid == 0) {
        __threadfence();                            // publish partials (release)
        const int old = atomicAdd(&g_cnt[b], 1);
        lastFlag = (old == SPLIT - 1) ? 1 : 0;
        __threadfence();                            // acquire
    }
    __syncthreads();

    if (lastFlag) {
        if (tid < NVAL) {
            volatile float* vPb = g_Pb + (size_t)b * SPLIT * NVAL;
            float s = 0.f;
            #pragma unroll
            for (int s2 = 0; s2 < SPLIT; s2++) s += vPb[s2 * NVAL + tid];
            num[tid] = s * g_EV[b * NVAL + tid];
        }
        __syncthreads();
        if (tid < 32) {
            float zz = num[tid] + num[tid + 32];
            #pragma unroll
            for (int o = 16; o > 0; o >>= 1) zz += __shfl_xor_sync(0xffffffffu, zz, o);
            if (tid == 0) num[0] = __frcp_rn(zz);   // reuse slot… careful: see below
        }
        __syncthreads();
        if (tid < NVAL) {
            // num[0] was overwritten by 1/Z AFTER it was read into zz; recompute
            // safe output: re-read EV*sum only for tid==0 case via registers.
            // To keep it simple and correct, tid 0 stashed rcpZ in num[0]; the
            // original num[0] value is recovered below.
            float val = (tid == 0) ? 0.f : num[tid];
            float rcpZ = num[0];
            if (tid == 0) {
                volatile float* vPb = g_Pb + (size_t)b * SPLIT * NVAL;
                float s = 0.f;
                #pragma unroll
                for (int s2 = 0; s2 < SPLIT; s2++) s += vPb[s2 * NVAL];
                val = s * g_EV[b * NVAL];
            }
            out[b * NVAL + tid] = val * rcpZ;
        }
        __syncthreads();
        if (tid == 0) g_cnt[b] = 0;                 // re-arm for next replay
    }
}

// ---------------------------------------------------------------------------
// Inputs (metadata order): x(int32), q(int32), embK, Wk_w, Wk_b, Wq_w, Wq_b.
// Wk_b is softmax-invariant (constant per batch) and intentionally unused.
// ---------------------------------------------------------------------------
extern "C" void kernel_launch(void* const* d_in, const int* in_sizes, int n_in,
                              void* d_out, int out_size)
{
    const int*   x    = (const int*)  d_in[0];
    const int*   q    = (const int*)  d_in[1];
    const float* embK = (const float*)d_in[2];
    const float* Wk_w = (const float*)d_in[3];
    const float* Wq_w = (const float*)d_in[5];
    const float* Wq_b = (const float*)d_in[6];
    float* out = (float*)d_out;

    tables_kernel<<<BS * 4, 256>>>(q, embK, Wk_w, Wq_w, Wq_b);
    attn_kernel<<<BS * SPLIT, 256>>>(x, out);
}